// round 15
// baseline (speedup 1.0000x reference)
#include <cuda_runtime.h>
#include <cuda_bf16.h>
#include <math.h>
#include <cstdint>

#define B_  4
#define C_  64
#define O_  64
#define H_  128
#define W_  128
#define K2_ 9
#define OCOFF 27
#define HW_ (H_ * W_)

#define SWZ(a) ((a) ^ (((a) >> 3) & 0x70))

// scratch
__device__ float g_off[B_ * OCOFF * HW_];            // offsets/mask [b][27][h][w]
__device__ __nv_bfloat16 g_fth[B_ * HW_ * C_];       // feat hi [b][h][w][c]
__device__ __nv_bfloat16 g_ftl[B_ * HW_ * C_];       // feat lo
__device__ __nv_bfloat16 g_wbh [K2_ * O_ * C_];      // w_def hi  [k][o64][c] swz
__device__ __nv_bfloat16 g_wbl [K2_ * O_ * C_];      // w_def lo
__device__ __nv_bfloat16 g_wobh[K2_ * 32 * C_];      // w_off hi  [k][o32][c] swz
__device__ __nv_bfloat16 g_wobl[K2_ * 32 * C_];      // w_off lo

// ===========================================================================
// ldmatrix + mma.sync (plain compute_103 path)
// ===========================================================================
__device__ __forceinline__ uint32_t smem_to_u32(const void* smem_ptr) {
    uint32_t addr;
    asm("{ .reg .u64 tmp; cvta.to.shared.u64 tmp, %1; cvt.u32.u64 %0, tmp; }"
        : "=r"(addr) : "l"(smem_ptr));
    return addr;
}

#define LDSM_X4(r, addr) \
    asm volatile("ldmatrix.sync.aligned.m8n8.x4.shared.b16 {%0,%1,%2,%3}, [%4];" \
        : "=r"((r)[0]), "=r"((r)[1]), "=r"((r)[2]), "=r"((r)[3]) \
        : "r"(addr))

#define MMA_BF16(d, a, b0, b1) \
    asm volatile("mma.sync.aligned.m16n8k16.row.col.f32.bf16.bf16.f32 " \
        "{%0,%1,%2,%3}, {%4,%5,%6,%7}, {%8,%9}, {%0,%1,%2,%3};" \
        : "+f"((d)[0]), "+f"((d)[1]), "+f"((d)[2]), "+f"((d)[3]) \
        : "r"((a)[0]), "r"((a)[1]), "r"((a)[2]), "r"((a)[3]), \
          "r"(b0), "r"(b1))

// ===========================================================================
// Kernel 0: weight prep — bf16 hi/lo splits, SW128-swizzled [k][o][c] tiles.
// ===========================================================================
__global__ void prep_w_kernel(const float* __restrict__ w_off,
                              const float* __restrict__ w_def) {
    int i = blockIdx.x * 256 + threadIdx.x;
    if (i < K2_ * O_ * C_) {
        int k = i >> 12;
        int r = i & 4095;
        int o = r >> 6;
        int c = r & 63;
        float w = w_def[(o * C_ + c) * K2_ + k];
        __nv_bfloat16 hb = __float2bfloat16(w);
        __nv_bfloat16 lb = __float2bfloat16(w - __bfloat162float(hb));
        int sw = SWZ(o * 128 + c * 2) >> 1;
        g_wbh[k * 4096 + sw] = hb;
        g_wbl[k * 4096 + sw] = lb;
    }
    if (i < K2_ * 32 * C_) {
        int k = i >> 11;
        int r = i & 2047;
        int o = r >> 6;
        int c = r & 63;
        float w = (o < OCOFF) ? w_off[(o * C_ + c) * K2_ + k] : 0.f;
        __nv_bfloat16 hb = __float2bfloat16(w);
        __nv_bfloat16 lb = __float2bfloat16(w - __bfloat162float(hb));
        int sw = SWZ(o * 128 + c * 2) >> 1;
        g_wobh[k * 2048 + sw] = hb;
        g_wobl[k * 2048 + sw] = lb;
    }
}

// ===========================================================================
// Kernel 1: feat transform.  feat [b][c][h][w] -> g_fth/g_ftl [b][h][w][c]
// ===========================================================================
__global__ __launch_bounds__(256) void feat_split_kernel(
    const float* __restrict__ feat) {
    __shared__ float s[C_ * 129];
    int blk = blockIdx.x;
    int h   = blk & (H_ - 1);
    int b   = blk >> 7;
    int t   = threadIdx.x;

    for (int i = t; i < C_ * W_; i += 256) {
        int c = i >> 7;
        int w = i & 127;
        s[c * 129 + w] = feat[((size_t)(b * C_ + c) * H_ + h) * W_ + w];
    }
    __syncthreads();
    {
        size_t base = ((size_t)b * HW_ + (size_t)h * W_) * C_;
        for (int i = t; i < C_ * W_; i += 256) {
            int w = i >> 6;
            int c = i & 63;
            float v = s[c * 129 + w];
            __nv_bfloat16 hb = __float2bfloat16(v);
            __nv_bfloat16 lb = __float2bfloat16(v - __bfloat162float(hb));
            g_fth[base + (size_t)w * C_ + c] = hb;
            g_ftl[base + (size_t)w * C_ + c] = lb;
        }
    }
}

// ===========================================================================
// Kernel 2: offset/mask conv via mma.sync.  Block = (b, h) -> M=128 px,
// N=32, K=576.  8 warps.  Single-buffered (R13-proven), 3 CTAs/SM target.
// Dynamic smem 40960 B: XH 16K | XL 16K | WH 4K | WL 4K.
// ===========================================================================
#define OC_XH  0
#define OC_XL  16384
#define OC_WH  32768
#define OC_WL  36864
#define OC_TOT 40960
#define OSTR   132

__global__ __launch_bounds__(256, 3) void offset_conv_kernel(
    const float* __restrict__ b_off) {
    extern __shared__ char smem[];
    const uint32_t sbase = smem_to_u32(smem);

    int t    = threadIdx.x;
    int wid  = t >> 5;
    int lane = t & 31;
    int blk  = blockIdx.x;
    int h    = blk & (H_ - 1);
    int b    = blk >> 7;

    const int wb = wid * 16;
    const uint32_t aRowOff = (uint32_t)((wb + (lane & 15)) * 128 +
                                        ((lane >> 4) & 1) * 16);
    const uint32_t bRowOff = (uint32_t)((((lane & 7) + ((lane >> 4) & 1) * 8)) * 128 +
                                        ((lane >> 3) & 1) * 16);

    float acc[4][4] = {};

    for (int k = 0; k < K2_; k++) {
        int dy = k / 3 - 1;
        int dx = k % 3 - 1;
        int hs = h + dy;
        bool rowok = (hs >= 0) && (hs < H_);
        const uint4* srch = (const uint4*)(g_fth + ((size_t)b * HW_ + (size_t)hs * W_) * C_);
        const uint4* srcl = (const uint4*)(g_ftl + ((size_t)b * HW_ + (size_t)hs * W_) * C_);
        // ---- stage A tiles: 2048 uint4 (hi+lo), swizzled rows, zero pad ----
        for (int i = t; i < 2048; i += 256) {
            int buf = i >> 10;          // 0 = hi, 1 = lo
            int rem = i & 1023;
            int p   = rem >> 3;
            int ci  = rem & 7;
            int w   = p + dx;
            uint4 v = make_uint4(0u, 0u, 0u, 0u);
            if (rowok && w >= 0 && w < W_) {
                const uint4* src = buf ? srcl : srch;
                v = src[w * 8 + ci];
            }
            uint32_t dsto = (uint32_t)(p * 128) + ((uint32_t)(ci * 16) ^ (((uint32_t)p & 7u) << 4));
            *(uint4*)(smem + (buf ? OC_XL : OC_XH) + dsto) = v;
        }
        // ---- stage W tiles: 256 uint4 each ----
        {
            ((uint4*)(smem + OC_WH))[t & 255] = ((const uint4*)(g_wobh + k * 2048))[t & 255];
            ((uint4*)(smem + OC_WL))[t & 255] = ((const uint4*)(g_wobl + k * 2048))[t & 255];
        }
        __syncthreads();
        // ---- GEMM ----
#pragma unroll
        for (int kc = 0; kc < 4; kc++) {
            uint32_t ah[4], al[4];
            uint32_t aoff = SWZ(aRowOff + kc * 32);
            LDSM_X4(ah, sbase + OC_XH + aoff);
            LDSM_X4(al, sbase + OC_XL + aoff);
#pragma unroll
            for (int nt = 0; nt < 2; nt++) {
                uint32_t bh[4], bl[4];
                uint32_t boff = SWZ(bRowOff + (uint32_t)(nt * 16 * 128 + kc * 32));
                LDSM_X4(bh, sbase + OC_WH + boff);
                LDSM_X4(bl, sbase + OC_WL + boff);
                MMA_BF16(acc[nt * 2],     ah, bh[0], bh[1]);
                MMA_BF16(acc[nt * 2],     al, bh[0], bh[1]);
                MMA_BF16(acc[nt * 2],     ah, bl[0], bl[1]);
                MMA_BF16(acc[nt * 2 + 1], ah, bh[2], bh[3]);
                MMA_BF16(acc[nt * 2 + 1], al, bh[2], bh[3]);
                MMA_BF16(acc[nt * 2 + 1], ah, bl[2], bl[3]);
            }
        }
        __syncthreads();
    }

    // ---- epilogue: bias, sigmoid on mask channels, transpose, store ----
    float* s_out = (float*)smem;
    {
        int prow = wb + (lane >> 2);
#pragma unroll
        for (int g = 0; g < 4; g++) {
            int o0 = g * 8 + 2 * (lane & 3);
#pragma unroll
            for (int j = 0; j < 2; j++) {
                int o = o0 + j;
                float bb = (o < OCOFF) ? __ldg(b_off + o) : 0.f;
                float v0 = acc[g][j]     + bb;
                float v1 = acc[g][j + 2] + bb;
                if (o >= 18 && o < OCOFF) {
                    v0 = 1.f / (1.f + expf(-v0));
                    v1 = 1.f / (1.f + expf(-v1));
                }
                s_out[o * OSTR + prow]     = v0;
                s_out[o * OSTR + prow + 8] = v1;
            }
        }
    }
    __syncthreads();
    for (int i = t; i < OCOFF * 32; i += 256) {
        int o  = i >> 5;
        int pq = i & 31;
        float4 vv = *(const float4*)&s_out[o * OSTR + pq * 4];
        *(float4*)&g_off[((size_t)(b * OCOFF + o) * H_ + h) * W_ + pq * 4] = vv;
    }
}

// ===========================================================================
// Kernel 3: deformable sampling + mma.sync GEMM (R13-proven structure),
// 3 CTAs/SM target via __launch_bounds__(256, 3).
// Block = (b, h): M=128 px, N=64, K=576.  8 warps.
// Dynamic smem 49152 B: XH 16K | XL 16K | WH 8K | WL 8K.
// ===========================================================================
#define SM_XH  0
#define SM_XL  16384
#define SM_WH  32768
#define SM_WL  40960
#define SM_TOT 49152

__global__ __launch_bounds__(256, 3) void deform_gemm_kernel(
    const float* __restrict__ x, const float* __restrict__ b_def,
    float* __restrict__ out) {
    extern __shared__ char smem[];
    const uint32_t sbase = smem_to_u32(smem);

    int t    = threadIdx.x;
    int wid  = t >> 5;
    int lane = t & 31;
    int blk  = blockIdx.x;
    int h    = blk & (H_ - 1);
    int b    = blk >> 7;

    const float* xb = x + (size_t)b * C_ * HW_;
    const int sp = t & 127;        // sampled pixel (w coordinate)
    const int cg = (t >> 7) * 32;  // channel half

    const int wb = wid * 16;
    const uint32_t aRowOff = (uint32_t)((wb + (lane & 15)) * 128 +
                                        ((lane >> 4) & 1) * 16);
    const uint32_t bRowOff = (uint32_t)((((lane & 7) + ((lane >> 4) & 1) * 8)) * 128 +
                                        ((lane >> 3) & 1) * 16);

    float acc[8][4] = {};

    for (int k = 0; k < K2_; k++) {
        // ---- per-pixel bilinear setup ----
        int dy = k / 3 - 1;
        int dx = k % 3 - 1;
        int obase = (b * OCOFF * H_ + h) * W_ + sp;
        float ox = g_off[obase + (0 * 9 + k) * HW_];
        float oy = g_off[obase + (1 * 9 + k) * HW_];
        float m  = g_off[obase + (2 * 9 + k) * HW_];
        float ys = (float)(h + dy) + oy;
        float xs = (float)(sp + dx) + ox;
        float y0f = floorf(ys);
        float x0f = floorf(xs);
        float wy1 = ys - y0f;
        float wx1 = xs - x0f;
        int y0 = (int)y0f;
        int x0 = (int)x0f;
        int   iv[4];
        float wf[4];
#pragma unroll
        for (int cr = 0; cr < 4; cr++) {
            int oyc = cr >> 1;
            int oxc = cr & 1;
            int yy = y0 + oyc;
            int xx = x0 + oxc;
            float wgt = (oyc ? wy1 : 1.f - wy1) * (oxc ? wx1 : 1.f - wx1) * m;
            bool valid = (yy >= 0) && (yy < H_) && (xx >= 0) && (xx < W_);
            int yc = min(max(yy, 0), H_ - 1);
            int xc = min(max(xx, 0), W_ - 1);
            iv[cr] = yc * W_ + xc;
            wf[cr] = valid ? wgt : 0.f;
        }
        // ---- sample 32 channels for pixel sp, hi/lo split, swizzled stores ----
#pragma unroll
        for (int q = 0; q < 4; q++) {
            int c0 = cg + q * 8;
            float v[8];
#pragma unroll
            for (int j = 0; j < 8; j++) {
                const float* xc = xb + (c0 + j) * HW_;
                v[j] = wf[0] * __ldg(xc + iv[0]) + wf[1] * __ldg(xc + iv[1]) +
                       wf[2] * __ldg(xc + iv[2]) + wf[3] * __ldg(xc + iv[3]);
            }
            uint32_t hi[4];
            uint32_t lo[4];
#pragma unroll
            for (int mm = 0; mm < 4; mm++) {
                float a0 = v[2 * mm];
                float a1 = v[2 * mm + 1];
                __nv_bfloat16 h0 = __float2bfloat16(a0);
                __nv_bfloat16 h1 = __float2bfloat16(a1);
                __nv_bfloat16 l0 = __float2bfloat16(a0 - __bfloat162float(h0));
                __nv_bfloat16 l1 = __float2bfloat16(a1 - __bfloat162float(h1));
                hi[mm] = (uint32_t)__bfloat16_as_ushort(h0) |
                         ((uint32_t)__bfloat16_as_ushort(h1) << 16);
                lo[mm] = (uint32_t)__bfloat16_as_ushort(l0) |
                         ((uint32_t)__bfloat16_as_ushort(l1) << 16);
            }
            uint32_t so = SWZ((uint32_t)(sp * 128 + c0 * 2));
            *(uint4*)(smem + SM_XH + so) = make_uint4(hi[0], hi[1], hi[2], hi[3]);
            *(uint4*)(smem + SM_XL + so) = make_uint4(lo[0], lo[1], lo[2], lo[3]);
        }
        // ---- stage weight tiles ----
        {
            int i0 = t;
            int i1 = t + 256;
            ((float4*)(smem + SM_WH))[i0] = ((const float4*)(g_wbh + k * 4096))[i0];
            ((float4*)(smem + SM_WH))[i1] = ((const float4*)(g_wbh + k * 4096))[i1];
            ((float4*)(smem + SM_WL))[i0] = ((const float4*)(g_wbl + k * 4096))[i0];
            ((float4*)(smem + SM_WL))[i1] = ((const float4*)(g_wbl + k * 4096))[i1];
        }
        __syncthreads();
        // ---- GEMM: 3 split terms ----
#pragma unroll
        for (int kc = 0; kc < 4; kc++) {
            uint32_t ah[4], al[4];
            uint32_t aoff = SWZ(aRowOff + kc * 32);
            LDSM_X4(ah, sbase + SM_XH + aoff);
            LDSM_X4(al, sbase + SM_XL + aoff);
#pragma unroll
            for (int nt = 0; nt < 4; nt++) {
                uint32_t bh[4], bl[4];
                uint32_t boff = SWZ(bRowOff + (uint32_t)(nt * 16 * 128 + kc * 32));
                LDSM_X4(bh, sbase + SM_WH + boff);
                LDSM_X4(bl, sbase + SM_WL + boff);
                MMA_BF16(acc[nt * 2],     ah, bh[0], bh[1]);
                MMA_BF16(acc[nt * 2],     al, bh[0], bh[1]);
                MMA_BF16(acc[nt * 2],     ah, bl[0], bl[1]);
                MMA_BF16(acc[nt * 2 + 1], ah, bh[2], bh[3]);
                MMA_BF16(acc[nt * 2 + 1], al, bh[2], bh[3]);
                MMA_BF16(acc[nt * 2 + 1], ah, bl[2], bl[3]);
            }
        }
        __syncthreads();
    }

    // ---- epilogue: fragments -> padded smem [o][OSTR] -> coalesced STG ----
    float* s_out = (float*)smem;
    {
        int prow = wb + (lane >> 2);
#pragma unroll
        for (int nt2 = 0; nt2 < 8; nt2++) {
            int o0 = nt2 * 8 + 2 * (lane & 3);
            float b0 = __ldg(b_def + o0);
            float b1 = __ldg(b_def + o0 + 1);
            s_out[o0 * OSTR + prow]           = fmaxf(acc[nt2][0] + b0, 0.f);
            s_out[(o0 + 1) * OSTR + prow]     = fmaxf(acc[nt2][1] + b1, 0.f);
            s_out[o0 * OSTR + prow + 8]       = fmaxf(acc[nt2][2] + b0, 0.f);
            s_out[(o0 + 1) * OSTR + prow + 8] = fmaxf(acc[nt2][3] + b1, 0.f);
        }
    }
    __syncthreads();
    for (int i = t; i < 2048; i += 256) {
        int o  = i >> 5;
        int pq = i & 31;
        float4 vv = *(const float4*)&s_out[o * OSTR + pq * 4];
        *(float4*)&out[(((size_t)b * O_ + o) * H_ + h) * W_ + pq * 4] = vv;
    }
}

// ===========================================================================
extern "C" void kernel_launch(void* const* d_in, const int* in_sizes, int n_in,
                              void* d_out, int out_size) {
    const float* x     = (const float*)d_in[0];
    const float* feat  = (const float*)d_in[1];
    const float* w_off = (const float*)d_in[2];
    const float* b_off = (const float*)d_in[3];
    const float* w_def = (const float*)d_in[4];
    const float* b_def = (const float*)d_in[5];
    float* out = (float*)d_out;

    prep_w_kernel<<<(K2_ * O_ * C_ + 255) / 256, 256>>>(w_off, w_def);
    feat_split_kernel<<<B_ * H_, 256>>>(feat);
    offset_conv_kernel<<<B_ * H_, 256, OC_TOT>>>(b_off);
    deform_gemm_kernel<<<B_ * H_, 256, SM_TOT>>>(x, b_def, out);
}

// round 16
// speedup vs baseline: 1.2973x; 1.2973x over previous
#include <cuda_runtime.h>
#include <cuda_bf16.h>
#include <cuda_fp16.h>
#include <math.h>
#include <cstdint>

#define B_  4
#define C_  64
#define O_  64
#define H_  128
#define W_  128
#define K2_ 9
#define OCOFF 27
#define HW_ (H_ * W_)

#define SWZ(a) ((a) ^ (((a) >> 3) & 0x70))

// scratch
__device__ float g_off[B_ * OCOFF * HW_];            // offsets/mask [b][27][h][w]
__device__ __nv_bfloat16 g_fth[B_ * HW_ * C_];       // feat hi [b][h][w][c]
__device__ __nv_bfloat16 g_ftl[B_ * HW_ * C_];       // feat lo
__device__ __half        g_wf16[K2_ * O_ * C_];      // w_def fp16 [k][o64][c] swz
__device__ __nv_bfloat16 g_wobh[K2_ * 32 * C_];      // w_off hi  [k][o32][c] swz
__device__ __nv_bfloat16 g_wobl[K2_ * 32 * C_];      // w_off lo

// ===========================================================================
// ldmatrix + mma.sync (plain compute_103 path)
// ===========================================================================
__device__ __forceinline__ uint32_t smem_to_u32(const void* smem_ptr) {
    uint32_t addr;
    asm("{ .reg .u64 tmp; cvta.to.shared.u64 tmp, %1; cvt.u32.u64 %0, tmp; }"
        : "=r"(addr) : "l"(smem_ptr));
    return addr;
}

#define LDSM_X4(r, addr) \
    asm volatile("ldmatrix.sync.aligned.m8n8.x4.shared.b16 {%0,%1,%2,%3}, [%4];" \
        : "=r"((r)[0]), "=r"((r)[1]), "=r"((r)[2]), "=r"((r)[3]) \
        : "r"(addr))

#define MMA_BF16(d, a, b0, b1) \
    asm volatile("mma.sync.aligned.m16n8k16.row.col.f32.bf16.bf16.f32 " \
        "{%0,%1,%2,%3}, {%4,%5,%6,%7}, {%8,%9}, {%0,%1,%2,%3};" \
        : "+f"((d)[0]), "+f"((d)[1]), "+f"((d)[2]), "+f"((d)[3]) \
        : "r"((a)[0]), "r"((a)[1]), "r"((a)[2]), "r"((a)[3]), \
          "r"(b0), "r"(b1))

#define MMA_FP16(d, a, b0, b1) \
    asm volatile("mma.sync.aligned.m16n8k16.row.col.f32.f16.f16.f32 " \
        "{%0,%1,%2,%3}, {%4,%5,%6,%7}, {%8,%9}, {%0,%1,%2,%3};" \
        : "+f"((d)[0]), "+f"((d)[1]), "+f"((d)[2]), "+f"((d)[3]) \
        : "r"((a)[0]), "r"((a)[1]), "r"((a)[2]), "r"((a)[3]), \
          "r"(b0), "r"(b1))

// ===========================================================================
// Kernel 0: weight prep.  w_def -> fp16 single [k][o][c] swz (deform GEMM);
// w_off -> bf16 hi/lo swz (offset conv, unchanged).
// ===========================================================================
__global__ void prep_w_kernel(const float* __restrict__ w_off,
                              const float* __restrict__ w_def) {
    int i = blockIdx.x * 256 + threadIdx.x;
    if (i < K2_ * O_ * C_) {
        int k = i >> 12;
        int r = i & 4095;
        int o = r >> 6;
        int c = r & 63;
        float w = w_def[(o * C_ + c) * K2_ + k];
        int sw = SWZ(o * 128 + c * 2) >> 1;
        g_wf16[k * 4096 + sw] = __float2half(w);
    }
    if (i < K2_ * 32 * C_) {
        int k = i >> 11;
        int r = i & 2047;
        int o = r >> 6;
        int c = r & 63;
        float w = (o < OCOFF) ? w_off[(o * C_ + c) * K2_ + k] : 0.f;
        __nv_bfloat16 hb = __float2bfloat16(w);
        __nv_bfloat16 lb = __float2bfloat16(w - __bfloat162float(hb));
        int sw = SWZ(o * 128 + c * 2) >> 1;
        g_wobh[k * 2048 + sw] = hb;
        g_wobl[k * 2048 + sw] = lb;
    }
}

// ===========================================================================
// Kernel 1: feat transform.  feat [b][c][h][w] -> g_fth/g_ftl [b][h][w][c]
// ===========================================================================
__global__ __launch_bounds__(256) void feat_split_kernel(
    const float* __restrict__ feat) {
    __shared__ float s[C_ * 129];
    int blk = blockIdx.x;
    int h   = blk & (H_ - 1);
    int b   = blk >> 7;
    int t   = threadIdx.x;

    for (int i = t; i < C_ * W_; i += 256) {
        int c = i >> 7;
        int w = i & 127;
        s[c * 129 + w] = feat[((size_t)(b * C_ + c) * H_ + h) * W_ + w];
    }
    __syncthreads();
    {
        size_t base = ((size_t)b * HW_ + (size_t)h * W_) * C_;
        for (int i = t; i < C_ * W_; i += 256) {
            int w = i >> 6;
            int c = i & 63;
            float v = s[c * 129 + w];
            __nv_bfloat16 hb = __float2bfloat16(v);
            __nv_bfloat16 lb = __float2bfloat16(v - __bfloat162float(hb));
            g_fth[base + (size_t)w * C_ + c] = hb;
            g_ftl[base + (size_t)w * C_ + c] = lb;
        }
    }
}

// ===========================================================================
// Kernel 2: offset/mask conv via mma.sync (R13-proven, bf16 3-term).
// Block = (b, h): M=128 px, N=32, K=576.  8 warps.
// Dynamic smem 40960 B: XH 16K | XL 16K | WH 4K | WL 4K.
// ===========================================================================
#define OC_XH  0
#define OC_XL  16384
#define OC_WH  32768
#define OC_WL  36864
#define OC_TOT 40960
#define OSTR   132

__global__ __launch_bounds__(256, 2) void offset_conv_kernel(
    const float* __restrict__ b_off) {
    extern __shared__ char smem[];
    const uint32_t sbase = smem_to_u32(smem);

    int t    = threadIdx.x;
    int wid  = t >> 5;
    int lane = t & 31;
    int blk  = blockIdx.x;
    int h    = blk & (H_ - 1);
    int b    = blk >> 7;

    const int wb = wid * 16;
    const uint32_t aRowOff = (uint32_t)((wb + (lane & 15)) * 128 +
                                        ((lane >> 4) & 1) * 16);
    const uint32_t bRowOff = (uint32_t)((((lane & 7) + ((lane >> 4) & 1) * 8)) * 128 +
                                        ((lane >> 3) & 1) * 16);

    float acc[4][4] = {};

    for (int k = 0; k < K2_; k++) {
        int dy = k / 3 - 1;
        int dx = k % 3 - 1;
        int hs = h + dy;
        bool rowok = (hs >= 0) && (hs < H_);
        const uint4* srch = (const uint4*)(g_fth + ((size_t)b * HW_ + (size_t)hs * W_) * C_);
        const uint4* srcl = (const uint4*)(g_ftl + ((size_t)b * HW_ + (size_t)hs * W_) * C_);
        // ---- stage A tiles: 2048 uint4 (hi+lo), swizzled rows, zero pad ----
        for (int i = t; i < 2048; i += 256) {
            int buf = i >> 10;          // 0 = hi, 1 = lo
            int rem = i & 1023;
            int p   = rem >> 3;
            int ci  = rem & 7;
            int w   = p + dx;
            uint4 v = make_uint4(0u, 0u, 0u, 0u);
            if (rowok && w >= 0 && w < W_) {
                const uint4* src = buf ? srcl : srch;
                v = src[w * 8 + ci];
            }
            uint32_t dsto = (uint32_t)(p * 128) + ((uint32_t)(ci * 16) ^ (((uint32_t)p & 7u) << 4));
            *(uint4*)(smem + (buf ? OC_XL : OC_XH) + dsto) = v;
        }
        // ---- stage W tiles: 256 uint4 each ----
        {
            ((uint4*)(smem + OC_WH))[t & 255] = ((const uint4*)(g_wobh + k * 2048))[t & 255];
            ((uint4*)(smem + OC_WL))[t & 255] = ((const uint4*)(g_wobl + k * 2048))[t & 255];
        }
        __syncthreads();
        // ---- GEMM ----
#pragma unroll
        for (int kc = 0; kc < 4; kc++) {
            uint32_t ah[4], al[4];
            uint32_t aoff = SWZ(aRowOff + kc * 32);
            LDSM_X4(ah, sbase + OC_XH + aoff);
            LDSM_X4(al, sbase + OC_XL + aoff);
#pragma unroll
            for (int nt = 0; nt < 2; nt++) {
                uint32_t bh[4], bl[4];
                uint32_t boff = SWZ(bRowOff + (uint32_t)(nt * 16 * 128 + kc * 32));
                LDSM_X4(bh, sbase + OC_WH + boff);
                LDSM_X4(bl, sbase + OC_WL + boff);
                MMA_BF16(acc[nt * 2],     ah, bh[0], bh[1]);
                MMA_BF16(acc[nt * 2],     al, bh[0], bh[1]);
                MMA_BF16(acc[nt * 2],     ah, bl[0], bl[1]);
                MMA_BF16(acc[nt * 2 + 1], ah, bh[2], bh[3]);
                MMA_BF16(acc[nt * 2 + 1], al, bh[2], bh[3]);
                MMA_BF16(acc[nt * 2 + 1], ah, bl[2], bl[3]);
            }
        }
        __syncthreads();
    }

    // ---- epilogue: bias, sigmoid on mask channels, transpose, store ----
    float* s_out = (float*)smem;
    {
        int prow = wb + (lane >> 2);
#pragma unroll
        for (int g = 0; g < 4; g++) {
            int o0 = g * 8 + 2 * (lane & 3);
#pragma unroll
            for (int j = 0; j < 2; j++) {
                int o = o0 + j;
                float bb = (o < OCOFF) ? __ldg(b_off + o) : 0.f;
                float v0 = acc[g][j]     + bb;
                float v1 = acc[g][j + 2] + bb;
                if (o >= 18 && o < OCOFF) {
                    v0 = 1.f / (1.f + expf(-v0));
                    v1 = 1.f / (1.f + expf(-v1));
                }
                s_out[o * OSTR + prow]     = v0;
                s_out[o * OSTR + prow + 8] = v1;
            }
        }
    }
    __syncthreads();
    for (int i = t; i < OCOFF * 32; i += 256) {
        int o  = i >> 5;
        int pq = i & 31;
        float4 vv = *(const float4*)&s_out[o * OSTR + pq * 4];
        *(float4*)&g_off[((size_t)(b * OCOFF + o) * H_ + h) * W_ + pq * 4] = vv;
    }
}

// ===========================================================================
// Kernel 3: deformable sampling + SINGLE-TERM fp16 mma.sync GEMM.
// Block = (b, h): M=128 px, N=64, K=576.  8 warps, warp tile 16px x 64o.
// Per tap per warp: 4 A-LDSM + 16 B-LDSM + 32 MMA (vs 40 LDSM + 96 MMA for
// the bf16 3-term scheme) — halves the l1tex wavefront load.
// Dynamic smem 34816 B: X fp16 16K @0 | W fp16 8K @16384 | epilogue 33792 @0
// ===========================================================================
#define SM_X   0
#define SM_W   16384
#define SM_TOT 34816

__global__ __launch_bounds__(256, 2) void deform_gemm_kernel(
    const float* __restrict__ x, const float* __restrict__ b_def,
    float* __restrict__ out) {
    extern __shared__ char smem[];
    const uint32_t sbase = smem_to_u32(smem);

    int t    = threadIdx.x;
    int wid  = t >> 5;
    int lane = t & 31;
    int blk  = blockIdx.x;
    int h    = blk & (H_ - 1);
    int b    = blk >> 7;

    const float* xb = x + (size_t)b * C_ * HW_;
    const int sp = t & 127;        // sampled pixel (w coordinate)
    const int cg = (t >> 7) * 32;  // channel half

    const int wb = wid * 16;
    const uint32_t aRowOff = (uint32_t)((wb + (lane & 15)) * 128 +
                                        ((lane >> 4) & 1) * 16);
    const uint32_t bRowOff = (uint32_t)((((lane & 7) + ((lane >> 4) & 1) * 8)) * 128 +
                                        ((lane >> 3) & 1) * 16);

    float acc[8][4] = {};

    for (int k = 0; k < K2_; k++) {
        // ---- per-pixel bilinear setup ----
        int dy = k / 3 - 1;
        int dx = k % 3 - 1;
        int obase = (b * OCOFF * H_ + h) * W_ + sp;
        float ox = g_off[obase + (0 * 9 + k) * HW_];
        float oy = g_off[obase + (1 * 9 + k) * HW_];
        float m  = g_off[obase + (2 * 9 + k) * HW_];
        float ys = (float)(h + dy) + oy;
        float xs = (float)(sp + dx) + ox;
        float y0f = floorf(ys);
        float x0f = floorf(xs);
        float wy1 = ys - y0f;
        float wx1 = xs - x0f;
        int y0 = (int)y0f;
        int x0 = (int)x0f;
        int   iv[4];
        float wf[4];
#pragma unroll
        for (int cr = 0; cr < 4; cr++) {
            int oyc = cr >> 1;
            int oxc = cr & 1;
            int yy = y0 + oyc;
            int xx = x0 + oxc;
            float wgt = (oyc ? wy1 : 1.f - wy1) * (oxc ? wx1 : 1.f - wx1) * m;
            bool valid = (yy >= 0) && (yy < H_) && (xx >= 0) && (xx < W_);
            int yc = min(max(yy, 0), H_ - 1);
            int xc = min(max(xx, 0), W_ - 1);
            iv[cr] = yc * W_ + xc;
            wf[cr] = valid ? wgt : 0.f;
        }
        // ---- sample 32 channels for pixel sp, fp16 pack, swizzled stores ----
#pragma unroll
        for (int q = 0; q < 4; q++) {
            int c0 = cg + q * 8;
            float v[8];
#pragma unroll
            for (int j = 0; j < 8; j++) {
                const float* xc = xb + (c0 + j) * HW_;
                v[j] = wf[0] * __ldg(xc + iv[0]) + wf[1] * __ldg(xc + iv[1]) +
                       wf[2] * __ldg(xc + iv[2]) + wf[3] * __ldg(xc + iv[3]);
            }
            uint32_t pk[4];
#pragma unroll
            for (int mm = 0; mm < 4; mm++) {
                __half2 h2 = __floats2half2_rn(v[2 * mm], v[2 * mm + 1]);
                pk[mm] = *reinterpret_cast<uint32_t*>(&h2);
            }
            uint32_t so = SWZ((uint32_t)(sp * 128 + c0 * 2));
            *(uint4*)(smem + SM_X + so) = make_uint4(pk[0], pk[1], pk[2], pk[3]);
        }
        // ---- stage weight tile: 512 uint4 (8 KB) ----
        {
            int i0 = t;
            int i1 = t + 256;
            ((float4*)(smem + SM_W))[i0] = ((const float4*)(g_wf16 + k * 4096))[i0];
            ((float4*)(smem + SM_W))[i1] = ((const float4*)(g_wf16 + k * 4096))[i1];
        }
        __syncthreads();
        // ---- GEMM: single fp16 term ----
#pragma unroll
        for (int kc = 0; kc < 4; kc++) {
            uint32_t a[4];
            LDSM_X4(a, sbase + SM_X + SWZ(aRowOff + kc * 32));
#pragma unroll
            for (int nt = 0; nt < 4; nt++) {
                uint32_t bq[4];
                LDSM_X4(bq, sbase + SM_W + SWZ(bRowOff + (uint32_t)(nt * 16 * 128 + kc * 32)));
                MMA_FP16(acc[nt * 2],     a, bq[0], bq[1]);
                MMA_FP16(acc[nt * 2 + 1], a, bq[2], bq[3]);
            }
        }
        __syncthreads();
    }

    // ---- epilogue: fragments -> padded smem [o][OSTR] -> coalesced STG ----
    float* s_out = (float*)smem;
    {
        int prow = wb + (lane >> 2);
#pragma unroll
        for (int nt2 = 0; nt2 < 8; nt2++) {
            int o0 = nt2 * 8 + 2 * (lane & 3);
            float b0 = __ldg(b_def + o0);
            float b1 = __ldg(b_def + o0 + 1);
            s_out[o0 * OSTR + prow]           = fmaxf(acc[nt2][0] + b0, 0.f);
            s_out[(o0 + 1) * OSTR + prow]     = fmaxf(acc[nt2][1] + b1, 0.f);
            s_out[o0 * OSTR + prow + 8]       = fmaxf(acc[nt2][2] + b0, 0.f);
            s_out[(o0 + 1) * OSTR + prow + 8] = fmaxf(acc[nt2][3] + b1, 0.f);
        }
    }
    __syncthreads();
    for (int i = t; i < 2048; i += 256) {
        int o  = i >> 5;
        int pq = i & 31;
        float4 vv = *(const float4*)&s_out[o * OSTR + pq * 4];
        *(float4*)&out[(((size_t)b * O_ + o) * H_ + h) * W_ + pq * 4] = vv;
    }
}

// ===========================================================================
extern "C" void kernel_launch(void* const* d_in, const int* in_sizes, int n_in,
                              void* d_out, int out_size) {
    const float* x     = (const float*)d_in[0];
    const float* feat  = (const float*)d_in[1];
    const float* w_off = (const float*)d_in[2];
    const float* b_off = (const float*)d_in[3];
    const float* w_def = (const float*)d_in[4];
    const float* b_def = (const float*)d_in[5];
    float* out = (float*)d_out;

    prep_w_kernel<<<(K2_ * O_ * C_ + 255) / 256, 256>>>(w_off, w_def);
    feat_split_kernel<<<B_ * H_, 256>>>(feat);
    offset_conv_kernel<<<B_ * H_, 256, OC_TOT>>>(b_off);
    deform_gemm_kernel<<<B_ * H_, 256, SM_TOT>>>(x, b_def, out);
}

// round 17
// speedup vs baseline: 1.5238x; 1.1746x over previous
#include <cuda_runtime.h>
#include <cuda_bf16.h>
#include <cuda_fp16.h>
#include <math.h>
#include <cstdint>

#define B_  4
#define C_  64
#define O_  64
#define H_  128
#define W_  128
#define K2_ 9
#define OCOFF 27
#define HW_ (H_ * W_)

#define SWZ(a) ((a) ^ (((a) >> 3) & 0x70))

// scratch
__device__ float g_off[B_ * OCOFF * HW_];            // offsets/mask [b][27][h][w]
__device__ __half2 g_xp [B_ * C_ * HW_];             // x pairs: (x[w], x[w+1]) fp16, [b][c][h][w]
__device__ __half  g_ft16[B_ * HW_ * C_];            // feat fp16 [b][h][w][c]
__device__ __half  g_wf16[K2_ * O_ * C_];            // w_def fp16 [k][o64][c] swz
__device__ __half  g_wof16[K2_ * 32 * C_];           // w_off fp16 [k][o32][c] swz

// ===========================================================================
// ldmatrix + mma.sync (plain compute_103 path)
// ===========================================================================
__device__ __forceinline__ uint32_t smem_to_u32(const void* smem_ptr) {
    uint32_t addr;
    asm("{ .reg .u64 tmp; cvta.to.shared.u64 tmp, %1; cvt.u32.u64 %0, tmp; }"
        : "=r"(addr) : "l"(smem_ptr));
    return addr;
}

#define LDSM_X4(r, addr) \
    asm volatile("ldmatrix.sync.aligned.m8n8.x4.shared.b16 {%0,%1,%2,%3}, [%4];" \
        : "=r"((r)[0]), "=r"((r)[1]), "=r"((r)[2]), "=r"((r)[3]) \
        : "r"(addr))

#define MMA_FP16(d, a, b0, b1) \
    asm volatile("mma.sync.aligned.m16n8k16.row.col.f32.f16.f16.f32 " \
        "{%0,%1,%2,%3}, {%4,%5,%6,%7}, {%8,%9}, {%0,%1,%2,%3};" \
        : "+f"((d)[0]), "+f"((d)[1]), "+f"((d)[2]), "+f"((d)[3]) \
        : "r"((a)[0]), "r"((a)[1]), "r"((a)[2]), "r"((a)[3]), \
          "r"(b0), "r"(b1))

// ===========================================================================
// Kernel 0: weight prep — fp16 [k][o][c] SW128-swizzled tiles for both GEMMs.
// ===========================================================================
__global__ void prep_w_kernel(const float* __restrict__ w_off,
                              const float* __restrict__ w_def) {
    int i = blockIdx.x * 256 + threadIdx.x;
    if (i < K2_ * O_ * C_) {
        int k = i >> 12;
        int r = i & 4095;
        int o = r >> 6;
        int c = r & 63;
        float w = w_def[(o * C_ + c) * K2_ + k];
        int sw = SWZ(o * 128 + c * 2) >> 1;
        g_wf16[k * 4096 + sw] = __float2half(w);
    }
    if (i < K2_ * 32 * C_) {
        int k = i >> 11;
        int r = i & 2047;
        int o = r >> 6;
        int c = r & 63;
        float w = (o < OCOFF) ? w_off[(o * C_ + c) * K2_ + k] : 0.f;
        int sw = SWZ(o * 128 + c * 2) >> 1;
        g_wof16[k * 2048 + sw] = __float2half(w);
    }
}

// ===========================================================================
// Kernel 1: input transform.  Block = (b, h) row.
//   x    -> g_xp  [b][c][h][w] fp16 pair (x[w], x[w+1 clamped])
//   feat -> g_ft16 [b][h][w][c] fp16 (transposed via smem)
// ===========================================================================
__global__ __launch_bounds__(256) void input_prep_kernel(
    const float* __restrict__ x, const float* __restrict__ feat) {
    __shared__ float s[C_ * 129];
    int blk = blockIdx.x;
    int h   = blk & (H_ - 1);
    int b   = blk >> 7;
    int t   = threadIdx.x;

    // ---- x pairs (no transpose; read/write along w) ----
    for (int i = t; i < C_ * W_; i += 256) {
        int c = i >> 7;
        int w = i & 127;
        size_t rowb = ((size_t)(b * C_ + c) * H_ + h) * W_;
        float v0 = x[rowb + w];
        float v1 = x[rowb + min(w + 1, W_ - 1)];
        g_xp[rowb + w] = __floats2half2_rn(v0, v1);
    }
    // ---- feat transpose -> fp16 [w][c] ----
    for (int i = t; i < C_ * W_; i += 256) {
        int c = i >> 7;
        int w = i & 127;
        s[c * 129 + w] = feat[((size_t)(b * C_ + c) * H_ + h) * W_ + w];
    }
    __syncthreads();
    {
        size_t base = ((size_t)b * HW_ + (size_t)h * W_) * C_;
        for (int i = t; i < C_ * W_; i += 256) {
            int w = i >> 6;
            int c = i & 63;
            g_ft16[base + (size_t)w * C_ + c] = __float2half(s[c * 129 + w]);
        }
    }
}

// ===========================================================================
// Kernel 2: offset/mask conv via single-term fp16 mma.sync.
// Block = (b, h): M=128 px, N=32, K=576.  8 warps.
// Dynamic smem 20480 B: X 16K | W 4K.
// ===========================================================================
#define OC_X   0
#define OC_W   16384
#define OC_TOT 20480
#define OSTR   132

__global__ __launch_bounds__(256, 2) void offset_conv_kernel(
    const float* __restrict__ b_off) {
    extern __shared__ char smem[];
    const uint32_t sbase = smem_to_u32(smem);

    int t    = threadIdx.x;
    int wid  = t >> 5;
    int lane = t & 31;
    int blk  = blockIdx.x;
    int h    = blk & (H_ - 1);
    int b    = blk >> 7;

    const int wb = wid * 16;
    const uint32_t aRowOff = (uint32_t)((wb + (lane & 15)) * 128 +
                                        ((lane >> 4) & 1) * 16);
    const uint32_t bRowOff = (uint32_t)((((lane & 7) + ((lane >> 4) & 1) * 8)) * 128 +
                                        ((lane >> 3) & 1) * 16);

    float acc[4][4] = {};

    for (int k = 0; k < K2_; k++) {
        int dy = k / 3 - 1;
        int dx = k % 3 - 1;
        int hs = h + dy;
        bool rowok = (hs >= 0) && (hs < H_);
        const uint4* src = (const uint4*)(g_ft16 + ((size_t)b * HW_ + (size_t)hs * W_) * C_);
        // ---- stage A tile: 1024 uint4, swizzled rows, zero pad ----
        for (int i = t; i < 1024; i += 256) {
            int p  = i >> 3;
            int ci = i & 7;
            int w  = p + dx;
            uint4 v = make_uint4(0u, 0u, 0u, 0u);
            if (rowok && w >= 0 && w < W_)
                v = src[w * 8 + ci];
            uint32_t dsto = (uint32_t)(p * 128) + ((uint32_t)(ci * 16) ^ (((uint32_t)p & 7u) << 4));
            *(uint4*)(smem + OC_X + dsto) = v;
        }
        // ---- stage W tile: 256 uint4 ----
        ((uint4*)(smem + OC_W))[t & 255] = ((const uint4*)(g_wof16 + k * 2048))[t & 255];
        __syncthreads();
        // ---- GEMM: single fp16 term ----
#pragma unroll
        for (int kc = 0; kc < 4; kc++) {
            uint32_t a[4];
            LDSM_X4(a, sbase + OC_X + SWZ(aRowOff + kc * 32));
#pragma unroll
            for (int nt = 0; nt < 2; nt++) {
                uint32_t bq[4];
                LDSM_X4(bq, sbase + OC_W + SWZ(bRowOff + (uint32_t)(nt * 16 * 128 + kc * 32)));
                MMA_FP16(acc[nt * 2],     a, bq[0], bq[1]);
                MMA_FP16(acc[nt * 2 + 1], a, bq[2], bq[3]);
            }
        }
        __syncthreads();
    }

    // ---- epilogue: bias, sigmoid on mask channels, transpose, store ----
    float* s_out = (float*)smem;
    {
        int prow = wb + (lane >> 2);
#pragma unroll
        for (int g = 0; g < 4; g++) {
            int o0 = g * 8 + 2 * (lane & 3);
#pragma unroll
            for (int j = 0; j < 2; j++) {
                int o = o0 + j;
                float bb = (o < OCOFF) ? __ldg(b_off + o) : 0.f;
                float v0 = acc[g][j]     + bb;
                float v1 = acc[g][j + 2] + bb;
                if (o >= 18 && o < OCOFF) {
                    v0 = 1.f / (1.f + expf(-v0));
                    v1 = 1.f / (1.f + expf(-v1));
                }
                s_out[o * OSTR + prow]     = v0;
                s_out[o * OSTR + prow + 8] = v1;
            }
        }
    }
    __syncthreads();
    for (int i = t; i < OCOFF * 32; i += 256) {
        int o  = i >> 5;
        int pq = i & 31;
        float4 vv = *(const float4*)&s_out[o * OSTR + pq * 4];
        *(float4*)&g_off[((size_t)(b * OCOFF + o) * H_ + h) * W_ + pq * 4] = vv;
    }
}

// ===========================================================================
// Kernel 3: deformable sampling (fp16 pair gathers: 2 LDG/c instead of 4)
// + single-term fp16 mma.sync GEMM (R16-proven).
// Block = (b, h): M=128 px, N=64, K=576.  8 warps.
// Dynamic smem 34816 B: X 16K | W 8K | epilogue 33792 @0.
// ===========================================================================
#define SM_X   0
#define SM_W   16384
#define SM_TOT 34816

__global__ __launch_bounds__(256, 2) void deform_gemm_kernel(
    const float* __restrict__ b_def, float* __restrict__ out) {
    extern __shared__ char smem[];
    const uint32_t sbase = smem_to_u32(smem);

    int t    = threadIdx.x;
    int wid  = t >> 5;
    int lane = t & 31;
    int blk  = blockIdx.x;
    int h    = blk & (H_ - 1);
    int b    = blk >> 7;

    const __half2* xpb = g_xp + (size_t)b * C_ * HW_;
    const int sp = t & 127;        // sampled pixel (w coordinate)
    const int cg = (t >> 7) * 32;  // channel half

    const int wb = wid * 16;
    const uint32_t aRowOff = (uint32_t)((wb + (lane & 15)) * 128 +
                                        ((lane >> 4) & 1) * 16);
    const uint32_t bRowOff = (uint32_t)((((lane & 7) + ((lane >> 4) & 1) * 8)) * 128 +
                                        ((lane >> 3) & 1) * 16);

    float acc[8][4] = {};

    for (int k = 0; k < K2_; k++) {
        // ---- per-pixel bilinear setup ----
        int dy = k / 3 - 1;
        int dx = k % 3 - 1;
        int obase = (b * OCOFF * H_ + h) * W_ + sp;
        float ox = g_off[obase + (0 * 9 + k) * HW_];
        float oy = g_off[obase + (1 * 9 + k) * HW_];
        float m  = g_off[obase + (2 * 9 + k) * HW_];
        float ys = (float)(h + dy) + oy;
        float xs = (float)(sp + dx) + ox;
        float y0f = floorf(ys);
        float x0f = floorf(xs);
        float wy1 = ys - y0f;
        float wx1 = xs - x0f;
        int y0 = (int)y0f;
        int x0 = (int)x0f;
        float wf[4];
#pragma unroll
        for (int cr = 0; cr < 4; cr++) {
            int oyc = cr >> 1;
            int oxc = cr & 1;
            int yy = y0 + oyc;
            int xx = x0 + oxc;
            float wgt = (oyc ? wy1 : 1.f - wy1) * (oxc ? wx1 : 1.f - wx1) * m;
            bool valid = (yy >= 0) && (yy < H_) && (xx >= 0) && (xx < W_);
            wf[cr] = valid ? wgt : 0.f;
        }
        int y0c = min(max(y0, 0), H_ - 1);
        int y1c = min(max(y0 + 1, 0), H_ - 1);
        int xc  = min(max(x0, 0), W_ - 1);
        bool selx = (x0 < 0);   // pair.x holds the x0+1 corner when x0 < 0
        int base0 = y0c * W_ + xc;
        int base1 = y1c * W_ + xc;
        // ---- gather 32 channels: 2 pair-loads per channel ----
#pragma unroll
        for (int q = 0; q < 4; q++) {
            int c0 = cg + q * 8;
            float v[8];
#pragma unroll
            for (int j = 0; j < 8; j++) {
                const __half2* pl = xpb + (size_t)(c0 + j) * HW_;
                __half2 pa = __ldg(pl + base0);
                __half2 pb = __ldg(pl + base1);
                float2 fa = __half22float2(pa);
                float2 fb = __half22float2(pb);
                float ax1 = selx ? fa.x : fa.y;
                float bx1 = selx ? fb.x : fb.y;
                v[j] = wf[0] * fa.x + wf[1] * ax1 + wf[2] * fb.x + wf[3] * bx1;
            }
            uint32_t pk[4];
#pragma unroll
            for (int mm = 0; mm < 4; mm++) {
                __half2 h2 = __floats2half2_rn(v[2 * mm], v[2 * mm + 1]);
                pk[mm] = *reinterpret_cast<uint32_t*>(&h2);
            }
            uint32_t so = SWZ((uint32_t)(sp * 128 + c0 * 2));
            *(uint4*)(smem + SM_X + so) = make_uint4(pk[0], pk[1], pk[2], pk[3]);
        }
        // ---- stage weight tile: 512 uint4 (8 KB) ----
        {
            int i0 = t;
            int i1 = t + 256;
            ((float4*)(smem + SM_W))[i0] = ((const float4*)(g_wf16 + k * 4096))[i0];
            ((float4*)(smem + SM_W))[i1] = ((const float4*)(g_wf16 + k * 4096))[i1];
        }
        __syncthreads();
        // ---- GEMM: single fp16 term ----
#pragma unroll
        for (int kc = 0; kc < 4; kc++) {
            uint32_t a[4];
            LDSM_X4(a, sbase + SM_X + SWZ(aRowOff + kc * 32));
#pragma unroll
            for (int nt = 0; nt < 4; nt++) {
                uint32_t bq[4];
                LDSM_X4(bq, sbase + SM_W + SWZ(bRowOff + (uint32_t)(nt * 16 * 128 + kc * 32)));
                MMA_FP16(acc[nt * 2],     a, bq[0], bq[1]);
                MMA_FP16(acc[nt * 2 + 1], a, bq[2], bq[3]);
            }
        }
        __syncthreads();
    }

    // ---- epilogue: fragments -> padded smem [o][OSTR] -> coalesced STG ----
    float* s_out = (float*)smem;
    {
        int prow = wb + (lane >> 2);
#pragma unroll
        for (int nt2 = 0; nt2 < 8; nt2++) {
            int o0 = nt2 * 8 + 2 * (lane & 3);
            float b0 = __ldg(b_def + o0);
            float b1 = __ldg(b_def + o0 + 1);
            s_out[o0 * OSTR + prow]           = fmaxf(acc[nt2][0] + b0, 0.f);
            s_out[(o0 + 1) * OSTR + prow]     = fmaxf(acc[nt2][1] + b1, 0.f);
            s_out[o0 * OSTR + prow + 8]       = fmaxf(acc[nt2][2] + b0, 0.f);
            s_out[(o0 + 1) * OSTR + prow + 8] = fmaxf(acc[nt2][3] + b1, 0.f);
        }
    }
    __syncthreads();
    for (int i = t; i < 2048; i += 256) {
        int o  = i >> 5;
        int pq = i & 31;
        float4 vv = *(const float4*)&s_out[o * OSTR + pq * 4];
        *(float4*)&out[(((size_t)b * O_ + o) * H_ + h) * W_ + pq * 4] = vv;
    }
}

// ===========================================================================
extern "C" void kernel_launch(void* const* d_in, const int* in_sizes, int n_in,
                              void* d_out, int out_size) {
    const float* x     = (const float*)d_in[0];
    const float* feat  = (const float*)d_in[1];
    const float* w_off = (const float*)d_in[2];
    const float* b_off = (const float*)d_in[3];
    const float* w_def = (const float*)d_in[4];
    const float* b_def = (const float*)d_in[5];
    float* out = (float*)d_out;

    prep_w_kernel<<<(K2_ * O_ * C_ + 255) / 256, 256>>>(w_off, w_def);
    input_prep_kernel<<<B_ * H_, 256>>>(x, feat);
    offset_conv_kernel<<<B_ * H_, 256, OC_TOT>>>(b_off);
    deform_gemm_kernel<<<B_ * H_, 256, SM_TOT>>>(b_def, out);
}